// round 3
// baseline (speedup 1.0000x reference)
#include <cuda_runtime.h>
#include <cstdint>

#define N_NODES 50000
#define N_EDGES 600000
#define D 128
#define NUM_LAYER 5

// ---------------- device scratch (allocation-free) ----------------
__device__ float g_z[N_NODES * D];        // z = h + agg   (GEMM1 input)
__device__ float g_t[N_NODES * 2 * D];    // hidden        (GEMM2 input)
__device__ float g_h[N_NODES * D];        // layer output
__device__ int   g_cnt[N_NODES];
__device__ int   g_rowstart[N_NODES + 1];
__device__ int   g_cursor[N_NODES];
__device__ int   g_srcs[N_EDGES];

// ---------------- helpers ----------------
__device__ __forceinline__ uint32_t f2tf(float x) {
    uint32_t r;
    asm("cvt.rna.tf32.f32 %0, %1;" : "=r"(r) : "f"(x));
    return r;
}

__device__ __forceinline__ void mma8(float* c, const uint32_t* a, const uint32_t* b) {
    asm volatile(
        "mma.sync.aligned.m16n8k8.row.col.f32.tf32.tf32.f32 "
        "{%0,%1,%2,%3}, {%4,%5,%6,%7}, {%8,%9}, {%0,%1,%2,%3};"
        : "+f"(c[0]), "+f"(c[1]), "+f"(c[2]), "+f"(c[3])
        : "r"(a[0]), "r"(a[1]), "r"(a[2]), "r"(a[3]), "r"(b[0]), "r"(b[1]));
}

__device__ __forceinline__ float lrelu(float v) {
    return v >= 0.0f ? v : 0.2f * v;
}

// ---------------- CSR build (edge_index is int32: JAX x64 disabled) -------
__global__ void k_zero_cnt() {
    int i = blockIdx.x * blockDim.x + threadIdx.x;
    if (i < N_NODES) g_cnt[i] = 0;
}

__global__ void k_hist(const int* __restrict__ ei) {
    int e = blockIdx.x * blockDim.x + threadIdx.x;
    if (e < N_EDGES) {
        int dst = ei[N_EDGES + e];
        if ((unsigned)dst < N_NODES) atomicAdd(&g_cnt[dst], 1);
    }
}

__global__ void k_scan() {
    __shared__ int s[1024];
    const int T = 1024;
    int tid = threadIdx.x;
    const int CH = (N_NODES + T - 1) / T;   // 49
    int base = tid * CH;
    int sum = 0;
    for (int i = 0; i < CH; i++) {
        int idx = base + i;
        if (idx < N_NODES) sum += g_cnt[idx];
    }
    s[tid] = sum;
    __syncthreads();
    // Hillis-Steele inclusive scan
    for (int off = 1; off < T; off <<= 1) {
        int v = (tid >= off) ? s[tid - off] : 0;
        __syncthreads();
        s[tid] += v;
        __syncthreads();
    }
    int run = (tid == 0) ? 0 : s[tid - 1];
    for (int i = 0; i < CH; i++) {
        int idx = base + i;
        if (idx < N_NODES) {
            g_rowstart[idx] = run;
            g_cursor[idx]   = run;
            run += g_cnt[idx];
        }
    }
    if (tid == T - 1) g_rowstart[N_NODES] = run;
}

__global__ void k_fill(const int* __restrict__ ei) {
    int e = blockIdx.x * blockDim.x + threadIdx.x;
    if (e < N_EDGES) {
        int src = ei[e];
        int dst = ei[N_EDGES + e];
        if ((unsigned)dst < N_NODES && (unsigned)src < N_NODES) {
            int p = atomicAdd(&g_cursor[dst], 1);
            g_srcs[p] = src;
        }
    }
}

// ---------------- gather aggregation: z[n] = h[n] + sum_{src->n} h[src] ----
__global__ void k_gather(const float* __restrict__ h, float* __restrict__ z) {
    int warp = (blockIdx.x * blockDim.x + threadIdx.x) >> 5;
    int lane = threadIdx.x & 31;
    if (warp >= N_NODES) return;
    const float4* hv = (const float4*)h;
    int s0 = g_rowstart[warp];
    int s1 = g_rowstart[warp + 1];
    float4 acc = __ldg(&hv[(size_t)warp * 32 + lane]);
    int e = s0;
    // 2-way edge ILP to cover L2 latency
    for (; e + 1 < s1; e += 2) {
        int sa = g_srcs[e], sb = g_srcs[e + 1];
        float4 va = __ldg(&hv[(size_t)sa * 32 + lane]);
        float4 vb = __ldg(&hv[(size_t)sb * 32 + lane]);
        acc.x += va.x + vb.x; acc.y += va.y + vb.y;
        acc.z += va.z + vb.z; acc.w += va.w + vb.w;
    }
    if (e < s1) {
        int sa = g_srcs[e];
        float4 va = __ldg(&hv[(size_t)sa * 32 + lane]);
        acc.x += va.x; acc.y += va.y; acc.z += va.z; acc.w += va.w;
    }
    ((float4*)z)[(size_t)warp * 32 + lane] = acc;
}

// ---------------- tf32 tensor-core GEMM: C = act(A[M,K] @ B[K,N] + bias) ----
// BM=128, BN=64, BK chunk=32; 8 warps (4x2), warp tile 32x32, mma m16n8k8.
__global__ __launch_bounds__(256) void k_gemm(
    const float* __restrict__ A, const float* __restrict__ B,
    const float* __restrict__ bias, float* __restrict__ C,
    int M, int K, int N, int leaky)
{
    const int BM = 128, BN = 64, BKC = 32;
    __shared__ uint32_t As[BM][BKC + 4];   // stride 36: conflict-free frag reads
    __shared__ uint32_t Bs[BKC][BN + 8];   // stride 72: conflict-free frag reads

    int tid  = threadIdx.x;
    int warp = tid >> 5;
    int lane = tid & 31;
    int wm = warp >> 1;       // 0..3
    int wn = warp & 1;        // 0..1
    int g  = lane >> 2;       // 0..7
    int tg = lane & 3;        // 0..3
    int m0 = blockIdx.x * BM;
    int n0 = blockIdx.y * BN;

    float acc[2][4][4];
#pragma unroll
    for (int a = 0; a < 2; a++)
#pragma unroll
        for (int b = 0; b < 4; b++)
#pragma unroll
            for (int c = 0; c < 4; c++) acc[a][b][c] = 0.0f;

    for (int k0 = 0; k0 < K; k0 += BKC) {
        // stage A tile (128 x 32)
#pragma unroll
        for (int i = 0; i < 4; i++) {
            int idx = tid + i * 256;           // 0..1023
            int r   = idx >> 3;
            int c4  = (idx & 7) * 4;
            float4 v = make_float4(0.f, 0.f, 0.f, 0.f);
            int gr = m0 + r;
            if (gr < M) v = __ldg((const float4*)&A[(size_t)gr * K + k0 + c4]);
            As[r][c4 + 0] = f2tf(v.x);
            As[r][c4 + 1] = f2tf(v.y);
            As[r][c4 + 2] = f2tf(v.z);
            As[r][c4 + 3] = f2tf(v.w);
        }
        // stage B tile (32 x 64)
#pragma unroll
        for (int i = 0; i < 2; i++) {
            int idx = tid + i * 256;           // 0..511
            int r   = idx >> 4;
            int c4  = (idx & 15) * 4;
            float4 v = __ldg((const float4*)&B[(size_t)(k0 + r) * N + n0 + c4]);
            Bs[r][c4 + 0] = f2tf(v.x);
            Bs[r][c4 + 1] = f2tf(v.y);
            Bs[r][c4 + 2] = f2tf(v.z);
            Bs[r][c4 + 3] = f2tf(v.w);
        }
        __syncthreads();

#pragma unroll
        for (int kk = 0; kk < BKC; kk += 8) {
            uint32_t af[2][4], bf[4][2];
#pragma unroll
            for (int mt = 0; mt < 2; mt++) {
                int mr = wm * 32 + mt * 16 + g;
                af[mt][0] = As[mr][kk + tg];
                af[mt][1] = As[mr + 8][kk + tg];
                af[mt][2] = As[mr][kk + tg + 4];
                af[mt][3] = As[mr + 8][kk + tg + 4];
            }
#pragma unroll
            for (int nt = 0; nt < 4; nt++) {
                int nc = wn * 32 + nt * 8 + g;
                bf[nt][0] = Bs[kk + tg][nc];
                bf[nt][1] = Bs[kk + tg + 4][nc];
            }
#pragma unroll
            for (int mt = 0; mt < 2; mt++)
#pragma unroll
                for (int nt = 0; nt < 4; nt++)
                    mma8(acc[mt][nt], af[mt], bf[nt]);
        }
        __syncthreads();
    }

    // epilogue: bias + optional leaky, float2 stores
#pragma unroll
    for (int mt = 0; mt < 2; mt++) {
#pragma unroll
        for (int nt = 0; nt < 4; nt++) {
            int row = m0 + wm * 32 + mt * 16 + g;
            int col = n0 + wn * 32 + nt * 8 + 2 * tg;
            float b0 = __ldg(&bias[col]);
            float b1 = __ldg(&bias[col + 1]);
            float v0 = acc[mt][nt][0] + b0;
            float v1 = acc[mt][nt][1] + b1;
            float v2 = acc[mt][nt][2] + b0;
            float v3 = acc[mt][nt][3] + b1;
            if (leaky) {
                v0 = lrelu(v0); v1 = lrelu(v1);
                v2 = lrelu(v2); v3 = lrelu(v3);
            }
            if (row < M) {
                float2 p = make_float2(v0, v1);
                *(float2*)&C[(size_t)row * N + col] = p;
            }
            if (row + 8 < M) {
                float2 p = make_float2(v2, v3);
                *(float2*)&C[(size_t)(row + 8) * N + col] = p;
            }
        }
    }
}

// ---------------- launch ----------------
extern "C" void kernel_launch(void* const* d_in, const int* in_sizes, int n_in,
                              void* d_out, int out_size) {
    const float* x  = (const float*)d_in[0];
    const int*   ei = (const int*)d_in[1];     // int32 (JAX x64 disabled)
    const float* W1 = (const float*)d_in[2];
    const float* b1 = (const float*)d_in[3];
    const float* W2 = (const float*)d_in[4];
    const float* b2 = (const float*)d_in[5];
    float*       out = (float*)d_out;

    float *zp, *tp, *hp;
    cudaGetSymbolAddress((void**)&zp, g_z);
    cudaGetSymbolAddress((void**)&tp, g_t);
    cudaGetSymbolAddress((void**)&hp, g_h);

    // CSR build (once per launch; edges identical across layers)
    k_zero_cnt<<<(N_NODES + 255) / 256, 256>>>();
    k_hist<<<(N_EDGES + 255) / 256, 256>>>(ei);
    k_scan<<<1, 1024>>>();
    k_fill<<<(N_EDGES + 255) / 256, 256>>>(ei);

    const int M = N_NODES;
    dim3 blk(256);
    dim3 grid_gather((N_NODES * 32 + 255) / 256);
    dim3 grid_g1((M + 127) / 128, (2 * D) / 64);  // 391 x 4
    dim3 grid_g2((M + 127) / 128, D / 64);        // 391 x 2

    const float* hin = x;
    for (int l = 0; l < NUM_LAYER; l++) {
        k_gather<<<grid_gather, blk>>>(hin, zp);
        k_gemm<<<grid_g1, blk>>>(zp, W1 + (size_t)l * D * 2 * D,
                                 b1 + (size_t)l * 2 * D, tp,
                                 M, D, 2 * D, 1);
        float* dst = (l == NUM_LAYER - 1) ? out : hp;
        k_gemm<<<grid_g2, blk>>>(tp, W2 + (size_t)l * 2 * D * D,
                                 b2 + (size_t)l * D, dst,
                                 M, 2 * D, D, (l < NUM_LAYER - 1) ? 1 : 0);
        hin = hp;
    }
}

// round 4
// speedup vs baseline: 1.0335x; 1.0335x over previous
#include <cuda_runtime.h>
#include <cstdint>

#define N_NODES 50000
#define N_EDGES 600000
#define D 128
#define NUM_LAYER 5

// ---------------- device scratch (allocation-free) ----------------
__device__ float g_z[N_NODES * D];        // z = h + agg   (GEMM1 input)
__device__ float g_t[N_NODES * 2 * D];    // hidden        (GEMM2 input)
__device__ float g_h[N_NODES * D];        // layer output
__device__ int   g_cnt[N_NODES];
__device__ int   g_rowstart[N_NODES + 1];
__device__ int   g_cursor[N_NODES];
__device__ int   g_srcs[N_EDGES];

// ---------------- helpers ----------------
__device__ __forceinline__ uint32_t f2tf(float x) {
    uint32_t r;
    asm("cvt.rna.tf32.f32 %0, %1;" : "=r"(r) : "f"(x));
    return r;
}

__device__ __forceinline__ void mma8(float* c, const uint32_t* a, const uint32_t* b) {
    asm volatile(
        "mma.sync.aligned.m16n8k8.row.col.f32.tf32.tf32.f32 "
        "{%0,%1,%2,%3}, {%4,%5,%6,%7}, {%8,%9}, {%0,%1,%2,%3};"
        : "+f"(c[0]), "+f"(c[1]), "+f"(c[2]), "+f"(c[3])
        : "r"(a[0]), "r"(a[1]), "r"(a[2]), "r"(a[3]), "r"(b[0]), "r"(b[1]));
}

__device__ __forceinline__ float lrelu(float v) {
    return v >= 0.0f ? v : 0.2f * v;
}

// ---------------- CSR build (edge_index is int32: JAX x64 disabled) -------
__global__ void k_zero_cnt() {
    int i = blockIdx.x * blockDim.x + threadIdx.x;
    if (i < N_NODES) g_cnt[i] = 0;
}

__global__ void k_hist(const int* __restrict__ ei) {
    int e = blockIdx.x * blockDim.x + threadIdx.x;
    if (e < N_EDGES) {
        int dst = ei[N_EDGES + e];
        if ((unsigned)dst < N_NODES) atomicAdd(&g_cnt[dst], 1);
    }
}

__global__ void k_scan() {
    __shared__ int s[1024];
    const int T = 1024;
    int tid = threadIdx.x;
    const int CH = (N_NODES + T - 1) / T;   // 49
    int base = tid * CH;
    int sum = 0;
    for (int i = 0; i < CH; i++) {
        int idx = base + i;
        if (idx < N_NODES) sum += g_cnt[idx];
    }
    s[tid] = sum;
    __syncthreads();
    for (int off = 1; off < T; off <<= 1) {
        int v = (tid >= off) ? s[tid - off] : 0;
        __syncthreads();
        s[tid] += v;
        __syncthreads();
    }
    int run = (tid == 0) ? 0 : s[tid - 1];
    for (int i = 0; i < CH; i++) {
        int idx = base + i;
        if (idx < N_NODES) {
            g_rowstart[idx] = run;
            g_cursor[idx]   = run;
            run += g_cnt[idx];
        }
    }
    if (tid == T - 1) g_rowstart[N_NODES] = run;
}

__global__ void k_fill(const int* __restrict__ ei) {
    int e = blockIdx.x * blockDim.x + threadIdx.x;
    if (e < N_EDGES) {
        int src = ei[e];
        int dst = ei[N_EDGES + e];
        if ((unsigned)dst < N_NODES && (unsigned)src < N_NODES) {
            int p = atomicAdd(&g_cursor[dst], 1);
            g_srcs[p] = src;
        }
    }
}

// ---------------- gather aggregation: z[n] = h[n] + sum_{src->n} h[src] ----
__global__ void k_gather(const float* __restrict__ h, float* __restrict__ z) {
    int warp = (blockIdx.x * blockDim.x + threadIdx.x) >> 5;
    int lane = threadIdx.x & 31;
    if (warp >= N_NODES) return;
    const float4* hv = (const float4*)h;
    int s0 = g_rowstart[warp];
    int s1 = g_rowstart[warp + 1];
    float4 acc = __ldg(&hv[(size_t)warp * 32 + lane]);
    int e = s0;
    for (; e + 1 < s1; e += 2) {
        int sa = g_srcs[e], sb = g_srcs[e + 1];
        float4 va = __ldg(&hv[(size_t)sa * 32 + lane]);
        float4 vb = __ldg(&hv[(size_t)sb * 32 + lane]);
        acc.x += va.x + vb.x; acc.y += va.y + vb.y;
        acc.z += va.z + vb.z; acc.w += va.w + vb.w;
    }
    if (e < s1) {
        int sa = g_srcs[e];
        float4 va = __ldg(&hv[(size_t)sa * 32 + lane]);
        acc.x += va.x; acc.y += va.y; acc.z += va.z; acc.w += va.w;
    }
    ((float4*)z)[(size_t)warp * 32 + lane] = acc;
}

// ---------------- tf32 tensor-core GEMM: C = act(A[M,K] @ B[K,N] + bias) ----
// BM=128, BN=64, BK=32; 8 warps (4x2), warp tile 32x32, mma m16n8k8.
// Software-pipelined: double-buffered smem, register prefetch of next chunk.
template <int K, int N, int LEAKY>
__global__ __launch_bounds__(256) void k_gemm(
    const float* __restrict__ A, const float* __restrict__ B,
    const float* __restrict__ bias, float* __restrict__ C)
{
    const int M = N_NODES;
    const int BM = 128, BN = 64, BK = 32;
    const int CHUNKS = K / BK;

    __shared__ uint32_t As[2][BM][BK + 4];   // stride 36
    __shared__ uint32_t Bs[2][BK][BN + 8];   // stride 72

    int tid  = threadIdx.x;
    int warp = tid >> 5;
    int lane = tid & 31;
    int wm = warp >> 1;       // 0..3
    int wn = warp & 1;        // 0..1
    int g  = lane >> 2;       // 0..7
    int tg = lane & 3;        // 0..3
    int m0 = blockIdx.x * BM;
    int n0 = blockIdx.y * BN;

    // staging indices
    const int ar = tid >> 3;              // 0..31 within 128 rows (x4 iters)
    const int ac = (tid & 7) * 4;         // 0,4,..28
    const int br = tid >> 4;              // 0..15 within 32 rows (x2 iters)
    const int bc = (tid & 15) * 4;        // 0,4,..60

    float4 areg[4], breg[2];
    const float4 zero4 = make_float4(0.f, 0.f, 0.f, 0.f);

    // prologue: load chunk 0
    {
        const int k0 = 0;
#pragma unroll
        for (int i = 0; i < 4; i++) {
            int r = ar + i * 32;
            int gr = m0 + r;
            areg[i] = (gr < M) ? __ldg((const float4*)&A[(size_t)gr * K + k0 + ac]) : zero4;
        }
#pragma unroll
        for (int i = 0; i < 2; i++) {
            int r = br + i * 16;
            breg[i] = __ldg((const float4*)&B[(size_t)(k0 + r) * N + n0 + bc]);
        }
    }
    // store chunk 0 to buf 0
#pragma unroll
    for (int i = 0; i < 4; i++) {
        int r = ar + i * 32;
        As[0][r][ac + 0] = f2tf(areg[i].x);
        As[0][r][ac + 1] = f2tf(areg[i].y);
        As[0][r][ac + 2] = f2tf(areg[i].z);
        As[0][r][ac + 3] = f2tf(areg[i].w);
    }
#pragma unroll
    for (int i = 0; i < 2; i++) {
        int r = br + i * 16;
        Bs[0][r][bc + 0] = f2tf(breg[i].x);
        Bs[0][r][bc + 1] = f2tf(breg[i].y);
        Bs[0][r][bc + 2] = f2tf(breg[i].z);
        Bs[0][r][bc + 3] = f2tf(breg[i].w);
    }
    __syncthreads();

    float acc[2][4][4];
#pragma unroll
    for (int a = 0; a < 2; a++)
#pragma unroll
        for (int b = 0; b < 4; b++)
#pragma unroll
            for (int c = 0; c < 4; c++) acc[a][b][c] = 0.0f;

#pragma unroll
    for (int ch = 0; ch < CHUNKS; ch++) {
        const int cur = ch & 1;
        const int nxt = cur ^ 1;

        // issue global loads for next chunk (latency hides behind mma below)
        if (ch + 1 < CHUNKS) {
            const int k0 = (ch + 1) * BK;
#pragma unroll
            for (int i = 0; i < 4; i++) {
                int r = ar + i * 32;
                int gr = m0 + r;
                areg[i] = (gr < M) ? __ldg((const float4*)&A[(size_t)gr * K + k0 + ac]) : zero4;
            }
#pragma unroll
            for (int i = 0; i < 2; i++) {
                int r = br + i * 16;
                breg[i] = __ldg((const float4*)&B[(size_t)(k0 + r) * N + n0 + bc]);
            }
        }

        // compute on current buffer
#pragma unroll
        for (int kk = 0; kk < BK; kk += 8) {
            uint32_t af[2][4], bf[4][2];
#pragma unroll
            for (int mt = 0; mt < 2; mt++) {
                int mr = wm * 32 + mt * 16 + g;
                af[mt][0] = As[cur][mr][kk + tg];
                af[mt][1] = As[cur][mr + 8][kk + tg];
                af[mt][2] = As[cur][mr][kk + tg + 4];
                af[mt][3] = As[cur][mr + 8][kk + tg + 4];
            }
#pragma unroll
            for (int nt = 0; nt < 4; nt++) {
                int nc = wn * 32 + nt * 8 + g;
                bf[nt][0] = Bs[cur][kk + tg][nc];
                bf[nt][1] = Bs[cur][kk + tg + 4][nc];
            }
#pragma unroll
            for (int mt = 0; mt < 2; mt++)
#pragma unroll
                for (int nt = 0; nt < 4; nt++)
                    mma8(acc[mt][nt], af[mt], bf[nt]);
        }

        // stage next chunk into alternate buffer
        if (ch + 1 < CHUNKS) {
#pragma unroll
            for (int i = 0; i < 4; i++) {
                int r = ar + i * 32;
                As[nxt][r][ac + 0] = f2tf(areg[i].x);
                As[nxt][r][ac + 1] = f2tf(areg[i].y);
                As[nxt][r][ac + 2] = f2tf(areg[i].z);
                As[nxt][r][ac + 3] = f2tf(areg[i].w);
            }
#pragma unroll
            for (int i = 0; i < 2; i++) {
                int r = br + i * 16;
                Bs[nxt][r][bc + 0] = f2tf(breg[i].x);
                Bs[nxt][r][bc + 1] = f2tf(breg[i].y);
                Bs[nxt][r][bc + 2] = f2tf(breg[i].z);
                Bs[nxt][r][bc + 3] = f2tf(breg[i].w);
            }
            __syncthreads();
        }
    }

    // epilogue: bias + optional leaky, float2 stores
#pragma unroll
    for (int mt = 0; mt < 2; mt++) {
#pragma unroll
        for (int nt = 0; nt < 4; nt++) {
            int row = m0 + wm * 32 + mt * 16 + g;
            int col = n0 + wn * 32 + nt * 8 + 2 * tg;
            float b0 = __ldg(&bias[col]);
            float b1 = __ldg(&bias[col + 1]);
            float v0 = acc[mt][nt][0] + b0;
            float v1 = acc[mt][nt][1] + b1;
            float v2 = acc[mt][nt][2] + b0;
            float v3 = acc[mt][nt][3] + b1;
            if (LEAKY) {
                v0 = lrelu(v0); v1 = lrelu(v1);
                v2 = lrelu(v2); v3 = lrelu(v3);
            }
            if (row < M) {
                float2 p = make_float2(v0, v1);
                *(float2*)&C[(size_t)row * N + col] = p;
            }
            if (row + 8 < M) {
                float2 p = make_float2(v2, v3);
                *(float2*)&C[(size_t)(row + 8) * N + col] = p;
            }
        }
    }
}

// ---------------- launch ----------------
extern "C" void kernel_launch(void* const* d_in, const int* in_sizes, int n_in,
                              void* d_out, int out_size) {
    const float* x  = (const float*)d_in[0];
    const int*   ei = (const int*)d_in[1];     // int32 (JAX x64 disabled)
    const float* W1 = (const float*)d_in[2];
    const float* b1 = (const float*)d_in[3];
    const float* W2 = (const float*)d_in[4];
    const float* b2 = (const float*)d_in[5];
    float*       out = (float*)d_out;

    float *zp, *tp, *hp;
    cudaGetSymbolAddress((void**)&zp, g_z);
    cudaGetSymbolAddress((void**)&tp, g_t);
    cudaGetSymbolAddress((void**)&hp, g_h);

    // CSR build (once per launch; edges identical across layers)
    k_zero_cnt<<<(N_NODES + 255) / 256, 256>>>();
    k_hist<<<(N_EDGES + 255) / 256, 256>>>(ei);
    k_scan<<<1, 1024>>>();
    k_fill<<<(N_EDGES + 255) / 256, 256>>>(ei);

    const int M = N_NODES;
    dim3 blk(256);
    dim3 grid_gather((N_NODES * 32 + 255) / 256);
    dim3 grid_g1((M + 127) / 128, (2 * D) / 64);  // 391 x 4
    dim3 grid_g2((M + 127) / 128, D / 64);        // 391 x 2

    const float* hin = x;
    for (int l = 0; l < NUM_LAYER; l++) {
        k_gather<<<grid_gather, blk>>>(hin, zp);
        k_gemm<128, 256, 1><<<grid_g1, blk>>>(zp, W1 + (size_t)l * D * 2 * D,
                                              b1 + (size_t)l * 2 * D, tp);
        float* dst = (l == NUM_LAYER - 1) ? out : hp;
        if (l < NUM_LAYER - 1)
            k_gemm<256, 128, 1><<<grid_g2, blk>>>(tp, W2 + (size_t)l * 2 * D * D,
                                                  b2 + (size_t)l * D, dst);
        else
            k_gemm<256, 128, 0><<<grid_g2, blk>>>(tp, W2 + (size_t)l * 2 * D * D,
                                                  b2 + (size_t)l * D, dst);
        hin = hp;
    }
}

// round 6
// speedup vs baseline: 1.1102x; 1.0743x over previous
#include <cuda_runtime.h>
#include <cstdint>

#define N_NODES 50000
#define N_EDGES 600000
#define D 128
#define NUM_LAYER 5

// ---------------- device scratch (allocation-free) ----------------
__device__ float g_z[N_NODES * D];         // z = h + agg, tf32-rounded (GEMM1 A)
__device__ float g_t[N_NODES * 2 * D];     // hidden, tf32-rounded     (GEMM2 A)
__device__ float g_h[N_NODES * D];         // layer output (f32)
__device__ int   g_cnt[N_NODES];
__device__ int   g_rowstart[N_NODES + 1];
__device__ int   g_cursor[N_NODES];
__device__ int   g_srcs[N_EDGES];
__device__ float g_w1t[NUM_LAYER * D * 2 * D];  // [l][k=128][n=256], tf32 bits
__device__ float g_w2t[NUM_LAYER * 2 * D * D];  // [l][k=256][n=128], tf32 bits

// ---------------- helpers ----------------
__device__ __forceinline__ uint32_t f2tf(float x) {
    uint32_t r;
    asm("cvt.rna.tf32.f32 %0, %1;" : "=r"(r) : "f"(x));
    return r;
}
__device__ __forceinline__ float lrelu(float v) { return v >= 0.0f ? v : 0.2f * v; }

__device__ __forceinline__ void mma8(float* c, const uint32_t* a, const uint32_t* b) {
    asm volatile(
        "mma.sync.aligned.m16n8k8.row.col.f32.tf32.tf32.f32 "
        "{%0,%1,%2,%3}, {%4,%5,%6,%7}, {%8,%9}, {%0,%1,%2,%3};"
        : "+f"(c[0]), "+f"(c[1]), "+f"(c[2]), "+f"(c[3])
        : "r"(a[0]), "r"(a[1]), "r"(a[2]), "r"(a[3]), "r"(b[0]), "r"(b[1]));
}

__device__ __forceinline__ uint32_t smem_u32(const void* p) {
    uint32_t a;
    asm("{ .reg .u64 t; cvta.to.shared.u64 t, %1; cvt.u32.u64 %0, t; }" : "=r"(a) : "l"(p));
    return a;
}
__device__ __forceinline__ void cp16(uint32_t s, const void* g) {
    asm volatile("cp.async.cg.shared.global [%0], [%1], 16;" :: "r"(s), "l"(g));
}
__device__ __forceinline__ void cp16z(uint32_t s, const void* g, int srcsz) {
    asm volatile("cp.async.cg.shared.global [%0], [%1], 16, %2;" :: "r"(s), "l"(g), "r"(srcsz));
}
#define CP_COMMIT() asm volatile("cp.async.commit_group;" ::: "memory")
#define CP_WAIT(n)  asm volatile("cp.async.wait_group %0;" :: "n"(n) : "memory")

// ---------------- CSR build (edge_index is int32: JAX x64 disabled) -------
__global__ void k_zero_cnt() {
    int i = blockIdx.x * blockDim.x + threadIdx.x;
    if (i < N_NODES) g_cnt[i] = 0;
}
__global__ void k_hist(const int* __restrict__ ei) {
    int e = blockIdx.x * blockDim.x + threadIdx.x;
    if (e < N_EDGES) {
        int dst = ei[N_EDGES + e];
        if ((unsigned)dst < N_NODES) atomicAdd(&g_cnt[dst], 1);
    }
}
__global__ void k_scan() {
    __shared__ int s[1024];
    const int T = 1024;
    int tid = threadIdx.x;
    const int CH = (N_NODES + T - 1) / T;
    int base = tid * CH;
    int sum = 0;
    for (int i = 0; i < CH; i++) {
        int idx = base + i;
        if (idx < N_NODES) sum += g_cnt[idx];
    }
    s[tid] = sum;
    __syncthreads();
    for (int off = 1; off < T; off <<= 1) {
        int v = (tid >= off) ? s[tid - off] : 0;
        __syncthreads();
        s[tid] += v;
        __syncthreads();
    }
    int run = (tid == 0) ? 0 : s[tid - 1];
    for (int i = 0; i < CH; i++) {
        int idx = base + i;
        if (idx < N_NODES) {
            g_rowstart[idx] = run;
            g_cursor[idx]   = run;
            run += g_cnt[idx];
        }
    }
    if (tid == T - 1) g_rowstart[N_NODES] = run;
}
__global__ void k_fill(const int* __restrict__ ei) {
    int e = blockIdx.x * blockDim.x + threadIdx.x;
    if (e < N_EDGES) {
        int src = ei[e];
        int dst = ei[N_EDGES + e];
        if ((unsigned)dst < N_NODES && (unsigned)src < N_NODES) {
            int p = atomicAdd(&g_cursor[dst], 1);
            g_srcs[p] = src;
        }
    }
}

// ---------------- weight tf32 convert, layout unchanged [k][n] ------------
__global__ void k_wtrans(const float* __restrict__ W1, const float* __restrict__ W2) {
    const int HALF = NUM_LAYER * 2 * D * D;   // 163840
    int i = blockIdx.x * blockDim.x + threadIdx.x;
    if (i < HALF) {
        g_w1t[i] = __uint_as_float(f2tf(W1[i]));
    } else if (i < 2 * HALF) {
        int j = i - HALF;
        g_w2t[j] = __uint_as_float(f2tf(W2[j]));
    }
}

// ------ gather: z[n] = tf32(h[n] + sum_{src->n} h[src]) --------------------
__global__ void k_gather(const float* __restrict__ h, float* __restrict__ z) {
    int warp = (blockIdx.x * blockDim.x + threadIdx.x) >> 5;
    int lane = threadIdx.x & 31;
    if (warp >= N_NODES) return;
    const float4* hv = (const float4*)h;
    int s0 = g_rowstart[warp];
    int s1 = g_rowstart[warp + 1];
    float4 acc = __ldg(&hv[(size_t)warp * 32 + lane]);
    int e = s0;
    for (; e + 1 < s1; e += 2) {
        int sa = g_srcs[e], sb = g_srcs[e + 1];
        float4 va = __ldg(&hv[(size_t)sa * 32 + lane]);
        float4 vb = __ldg(&hv[(size_t)sb * 32 + lane]);
        acc.x += va.x + vb.x; acc.y += va.y + vb.y;
        acc.z += va.z + vb.z; acc.w += va.w + vb.w;
    }
    if (e < s1) {
        int sa = g_srcs[e];
        float4 va = __ldg(&hv[(size_t)sa * 32 + lane]);
        acc.x += va.x; acc.y += va.y; acc.z += va.z; acc.w += va.w;
    }
    // tf32-round so GEMM1 can cp.async the operand verbatim
    acc.x = __uint_as_float(f2tf(acc.x));
    acc.y = __uint_as_float(f2tf(acc.y));
    acc.z = __uint_as_float(f2tf(acc.z));
    acc.w = __uint_as_float(f2tf(acc.w));
    ((float4*)z)[(size_t)warp * 32 + lane] = acc;
}

// ---------------- tf32 mma.sync GEMM, cp.async staged ----------------------
// C = act(A[M,K] @ B[K,N] + bias). Block 128x128, 8 warps (4x2), warp 32x64.
// BK=32, 2-stage cp.async pipeline. A and B are pre-tf32 in gmem.
// ACT: 0 = none, 1 = leaky, 2 = leaky + tf32-round (output feeds next GEMM)
template <int K, int N, int ACT>
__global__ __launch_bounds__(256) void k_gemm(
    const float* __restrict__ A, const float* __restrict__ B,
    const float* __restrict__ bias, float* __restrict__ C)
{
    const int M = N_NODES;
    const int BK = 32;
    const int CHUNKS = K / BK;
    const int AS_STRIDE = 36;    // uints per row, 128 rows
    const int BS_STRIDE = 136;   // uints per row, 32 rows
    const int AS_SIZE = 128 * AS_STRIDE;   // 4608 uints
    const int BS_SIZE = 32 * BS_STRIDE;    // 4352 uints

    extern __shared__ uint32_t sm[];
    uint32_t* Asb[2] = { sm, sm + AS_SIZE };
    uint32_t* Bsb[2] = { sm + 2 * AS_SIZE, sm + 2 * AS_SIZE + BS_SIZE };

    int tid  = threadIdx.x;
    int warp = tid >> 5;
    int lane = tid & 31;
    int wm = warp >> 1;       // 0..3  (M offset 32*wm)
    int wn = warp & 1;        // 0..1  (N offset 64*wn)
    int g  = lane >> 2;       // 0..7
    int tg = lane & 3;        // 0..3
    int m0 = blockIdx.x * 128;
    int n0 = blockIdx.y * 128;

    // staging indices (per thread: 4 x 16B for A, 4 x 16B for B per chunk)
    const int a_r  = tid >> 1;               // pairs: seg = tid + j*256
    // A: 1024 segs, seg>>3 = row, (seg&7)*4 = uint col
    // B: 1024 segs, seg>>5 = row, (seg&31)*4 = uint col
    (void)a_r;

    auto stage = [&](int ch, int buf) {
        uint32_t abase = smem_u32(Asb[buf]);
        uint32_t bbase = smem_u32(Bsb[buf]);
#pragma unroll
        for (int j = 0; j < 4; j++) {
            int seg = tid + j * 256;
            int r   = seg >> 3;
            int cu  = (seg & 7) * 4;
            int gr  = m0 + r;
            uint32_t dst = abase + (uint32_t)(r * AS_STRIDE + cu) * 4u;
            const float* src = &A[(size_t)gr * K + ch * BK + cu];
            cp16z(dst, src, (gr < M) ? 16 : 0);
        }
#pragma unroll
        for (int j = 0; j < 4; j++) {
            int seg = tid + j * 256;
            int r   = seg >> 5;
            int cu  = (seg & 31) * 4;
            uint32_t dst = bbase + (uint32_t)(r * BS_STRIDE + cu) * 4u;
            const float* src = &B[(size_t)(ch * BK + r) * N + n0 + cu];
            cp16(dst, src);
        }
        CP_COMMIT();
    };

    // prologue: stage chunks 0 and 1
    stage(0, 0);
    if (CHUNKS > 1) stage(1, 1);

    float acc[2][8][4];
#pragma unroll
    for (int a = 0; a < 2; a++)
#pragma unroll
        for (int b = 0; b < 8; b++)
#pragma unroll
            for (int c = 0; c < 4; c++) acc[a][b][c] = 0.0f;

#pragma unroll
    for (int ch = 0; ch < CHUNKS; ch++) {
        const int buf = ch & 1;
        if (ch + 1 < CHUNKS) { CP_WAIT(1); } else { CP_WAIT(0); }
        __syncthreads();

        const uint32_t* As = Asb[buf];
        const uint32_t* Bs = Bsb[buf];
#pragma unroll
        for (int kk = 0; kk < BK; kk += 8) {
            uint32_t af[2][4], bf[8][2];
#pragma unroll
            for (int mt = 0; mt < 2; mt++) {
                int mr = wm * 32 + mt * 16 + g;
                af[mt][0] = As[mr * AS_STRIDE + kk + tg];
                af[mt][1] = As[(mr + 8) * AS_STRIDE + kk + tg];
                af[mt][2] = As[mr * AS_STRIDE + kk + tg + 4];
                af[mt][3] = As[(mr + 8) * AS_STRIDE + kk + tg + 4];
            }
#pragma unroll
            for (int nt = 0; nt < 8; nt++) {
                int nc = wn * 64 + nt * 8 + g;
                bf[nt][0] = Bs[(kk + tg) * BS_STRIDE + nc];
                bf[nt][1] = Bs[(kk + tg + 4) * BS_STRIDE + nc];
            }
#pragma unroll
            for (int mt = 0; mt < 2; mt++)
#pragma unroll
                for (int nt = 0; nt < 8; nt++)
                    mma8(acc[mt][nt], af[mt], bf[nt]);
        }
        __syncthreads();
        if (ch + 2 < CHUNKS) stage(ch + 2, buf);
    }

    // epilogue
#pragma unroll
    for (int mt = 0; mt < 2; mt++) {
#pragma unroll
        for (int nt = 0; nt < 8; nt++) {
            int row = m0 + wm * 32 + mt * 16 + g;
            int col = n0 + wn * 64 + nt * 8 + 2 * tg;
            float b0 = __ldg(&bias[col]);
            float b1 = __ldg(&bias[col + 1]);
            float v0 = acc[mt][nt][0] + b0;
            float v1 = acc[mt][nt][1] + b1;
            float v2 = acc[mt][nt][2] + b0;
            float v3 = acc[mt][nt][3] + b1;
            if (ACT >= 1) {
                v0 = lrelu(v0); v1 = lrelu(v1);
                v2 = lrelu(v2); v3 = lrelu(v3);
            }
            if (ACT == 2) {
                v0 = __uint_as_float(f2tf(v0));
                v1 = __uint_as_float(f2tf(v1));
                v2 = __uint_as_float(f2tf(v2));
                v3 = __uint_as_float(f2tf(v3));
            }
            if (row < M)
                *(float2*)&C[(size_t)row * N + col] = make_float2(v0, v1);
            if (row + 8 < M)
                *(float2*)&C[(size_t)(row + 8) * N + col] = make_float2(v2, v3);
        }
    }
}

// ---------------- launch ----------------
extern "C" void kernel_launch(void* const* d_in, const int* in_sizes, int n_in,
                              void* d_out, int out_size) {
    const float* x  = (const float*)d_in[0];
    const int*   ei = (const int*)d_in[1];     // int32 (JAX x64 disabled)
    const float* W1 = (const float*)d_in[2];
    const float* b1 = (const float*)d_in[3];
    const float* W2 = (const float*)d_in[4];
    const float* b2 = (const float*)d_in[5];
    float*       out = (float*)d_out;

    float *zp, *tp, *hp, *w1t, *w2t;
    cudaGetSymbolAddress((void**)&zp, g_z);
    cudaGetSymbolAddress((void**)&tp, g_t);
    cudaGetSymbolAddress((void**)&hp, g_h);
    cudaGetSymbolAddress((void**)&w1t, g_w1t);
    cudaGetSymbolAddress((void**)&w2t, g_w2t);

    const int SMEM = (2 * 128 * 36 + 2 * 32 * 136) * 4;   // 71680 B
    cudaFuncSetAttribute(k_gemm<128, 256, 2>, cudaFuncAttributeMaxDynamicSharedMemorySize, SMEM);
    cudaFuncSetAttribute(k_gemm<256, 128, 1>, cudaFuncAttributeMaxDynamicSharedMemorySize, SMEM);
    cudaFuncSetAttribute(k_gemm<256, 128, 0>, cudaFuncAttributeMaxDynamicSharedMemorySize, SMEM);

    // CSR build + weight tf32 convert (once per launch)
    k_zero_cnt<<<(N_NODES + 255) / 256, 256>>>();
    k_hist<<<(N_EDGES + 255) / 256, 256>>>(ei);
    k_wtrans<<<(2 * NUM_LAYER * 2 * D * D + 255) / 256, 256>>>(W1, W2);
    k_scan<<<1, 1024>>>();
    k_fill<<<(N_EDGES + 255) / 256, 256>>>(ei);

    const int M = N_NODES;
    const int MB = (M + 127) / 128;            // 391
    dim3 blk(256);
    dim3 grid_gather((N_NODES * 32 + 255) / 256);
    dim3 grid_g1(MB, 2);    // N=256, BN=128
    dim3 grid_g2(MB, 1);    // N=128, BN=128

    const float* hin = x;
    for (int l = 0; l < NUM_LAYER; l++) {
        k_gather<<<grid_gather, blk>>>(hin, zp);
        k_gemm<128, 256, 2><<<grid_g1, blk, SMEM>>>(zp, w1t + (size_t)l * D * 2 * D,
                                                    b1 + (size_t)l * 2 * D, tp);
        float* dst = (l == NUM_LAYER - 1) ? out : hp;
        if (l < NUM_LAYER - 1)
            k_gemm<256, 128, 1><<<grid_g2, blk, SMEM>>>(tp, w2t + (size_t)l * 2 * D * D,
                                                        b2 + (size_t)l * D, dst);
        else
            k_gemm<256, 128, 0><<<grid_g2, blk, SMEM>>>(tp, w2t + (size_t)l * 2 * D * D,
                                                        b2 + (size_t)l * D, dst);
        hin = hp;
    }
}

// round 7
// speedup vs baseline: 1.2917x; 1.1635x over previous
#include <cuda_runtime.h>
#include <cstdint>

#define N_NODES 50000
#define N_EDGES 600000
#define D 128
#define NUM_LAYER 5

#define SCAN_BLK 256
#define N_SCAN_BLKS ((N_NODES + SCAN_BLK - 1) / SCAN_BLK)   // 196

// ---------------- device scratch (allocation-free) ----------------
__device__ float g_z[N_NODES * D];         // z = h + agg, tf32-rounded (GEMM1 A)
__device__ float g_t[N_NODES * 2 * D];     // hidden, tf32-rounded     (GEMM2 A)
__device__ float g_h[N_NODES * D];         // layer output (f32)
__device__ int   g_cnt[N_NODES];
__device__ int   g_rowstart[N_NODES + 1];
__device__ int   g_cursor[N_NODES];
__device__ int   g_srcs[N_EDGES];
__device__ int   g_blksum[N_SCAN_BLKS];
__device__ int   g_blkoff[N_SCAN_BLKS];
__device__ float g_w1t[NUM_LAYER * D * 2 * D];  // [l][k=128][n=256], tf32 bits
__device__ float g_w2t[NUM_LAYER * 2 * D * D];  // [l][k=256][n=128], tf32 bits

// ---------------- helpers ----------------
__device__ __forceinline__ uint32_t f2tf(float x) {
    uint32_t r;
    asm("cvt.rna.tf32.f32 %0, %1;" : "=r"(r) : "f"(x));
    return r;
}
__device__ __forceinline__ float lrelu(float v) { return v >= 0.0f ? v : 0.2f * v; }

__device__ __forceinline__ void mma8(float* c, const uint32_t* a, const uint32_t* b) {
    asm volatile(
        "mma.sync.aligned.m16n8k8.row.col.f32.tf32.tf32.f32 "
        "{%0,%1,%2,%3}, {%4,%5,%6,%7}, {%8,%9}, {%0,%1,%2,%3};"
        : "+f"(c[0]), "+f"(c[1]), "+f"(c[2]), "+f"(c[3])
        : "r"(a[0]), "r"(a[1]), "r"(a[2]), "r"(a[3]), "r"(b[0]), "r"(b[1]));
}

__device__ __forceinline__ uint32_t smem_u32(const void* p) {
    uint32_t a;
    asm("{ .reg .u64 t; cvta.to.shared.u64 t, %1; cvt.u32.u64 %0, t; }" : "=r"(a) : "l"(p));
    return a;
}
__device__ __forceinline__ void cp16(uint32_t s, const void* g) {
    asm volatile("cp.async.cg.shared.global [%0], [%1], 16;" :: "r"(s), "l"(g));
}
__device__ __forceinline__ void cp16z(uint32_t s, const void* g, int srcsz) {
    asm volatile("cp.async.cg.shared.global [%0], [%1], 16, %2;" :: "r"(s), "l"(g), "r"(srcsz));
}
#define CP_COMMIT() asm volatile("cp.async.commit_group;" ::: "memory")
#define CP_WAIT(n)  asm volatile("cp.async.wait_group %0;" :: "n"(n) : "memory")

// ---------------- CSR build (edge_index is int32: JAX x64 disabled) -------
__global__ void k_zero_cnt() {
    int i = blockIdx.x * blockDim.x + threadIdx.x;
    if (i < N_NODES) g_cnt[i] = 0;
}
__global__ void k_hist(const int* __restrict__ ei) {
    int e = blockIdx.x * blockDim.x + threadIdx.x;
    if (e < N_EDGES) {
        int dst = ei[N_EDGES + e];
        if ((unsigned)dst < N_NODES) atomicAdd(&g_cnt[dst], 1);
    }
}

// scan phase 1: per-block sums of g_cnt
__global__ void k_blocksum() {
    __shared__ int s[SCAN_BLK];
    int tid = threadIdx.x;
    int i = blockIdx.x * SCAN_BLK + tid;
    int v = (i < N_NODES) ? g_cnt[i] : 0;
    s[tid] = v;
    __syncthreads();
#pragma unroll
    for (int off = SCAN_BLK / 2; off > 0; off >>= 1) {
        if (tid < off) s[tid] += s[tid + off];
        __syncthreads();
    }
    if (tid == 0) g_blksum[blockIdx.x] = s[0];
}

// scan phase 2: exclusive scan of 196 block sums (single small block)
__global__ void k_scanblk() {
    __shared__ int s[256];
    int tid = threadIdx.x;
    int v = (tid < N_SCAN_BLKS) ? g_blksum[tid] : 0;
    s[tid] = v;
    __syncthreads();
#pragma unroll
    for (int off = 1; off < 256; off <<= 1) {
        int t = (tid >= off) ? s[tid - off] : 0;
        __syncthreads();
        s[tid] += t;
        __syncthreads();
    }
    if (tid < N_SCAN_BLKS) g_blkoff[tid] = s[tid] - v;   // exclusive
    if (tid == 255) g_rowstart[N_NODES] = s[N_SCAN_BLKS - 1];
}

// scan phase 3: block-local exclusive scan + block offset -> rowstart/cursor
__global__ void k_scatter() {
    __shared__ int s[SCAN_BLK];
    int tid = threadIdx.x;
    int i = blockIdx.x * SCAN_BLK + tid;
    int v = (i < N_NODES) ? g_cnt[i] : 0;
    s[tid] = v;
    __syncthreads();
#pragma unroll
    for (int off = 1; off < SCAN_BLK; off <<= 1) {
        int t = (tid >= off) ? s[tid - off] : 0;
        __syncthreads();
        s[tid] += t;
        __syncthreads();
    }
    if (i < N_NODES) {
        int rs = g_blkoff[blockIdx.x] + s[tid] - v;   // exclusive
        g_rowstart[i] = rs;
        g_cursor[i]   = rs;
    }
}

__global__ void k_fill(const int* __restrict__ ei) {
    int e = blockIdx.x * blockDim.x + threadIdx.x;
    if (e < N_EDGES) {
        int src = ei[e];
        int dst = ei[N_EDGES + e];
        if ((unsigned)dst < N_NODES && (unsigned)src < N_NODES) {
            int p = atomicAdd(&g_cursor[dst], 1);
            g_srcs[p] = src;
        }
    }
}

// ---------------- weight tf32 convert, layout unchanged [k][n] ------------
__global__ void k_wtrans(const float* __restrict__ W1, const float* __restrict__ W2) {
    const int HALF = NUM_LAYER * 2 * D * D;   // 163840
    int i = blockIdx.x * blockDim.x + threadIdx.x;
    if (i < HALF) {
        g_w1t[i] = __uint_as_float(f2tf(W1[i]));
    } else if (i < 2 * HALF) {
        int j = i - HALF;
        g_w2t[j] = __uint_as_float(f2tf(W2[j]));
    }
}

// ------ gather: z[n] = tf32(h[n] + sum_{src->n} h[src]) --------------------
__global__ void k_gather(const float* __restrict__ h, float* __restrict__ z) {
    int warp = (blockIdx.x * blockDim.x + threadIdx.x) >> 5;
    int lane = threadIdx.x & 31;
    if (warp >= N_NODES) return;
    const float4* hv = (const float4*)h;
    int s0 = g_rowstart[warp];
    int s1 = g_rowstart[warp + 1];
    float4 acc = __ldg(&hv[(size_t)warp * 32 + lane]);
    int e = s0;
    // 4-way edge ILP: 4 independent float4 loads in flight
    for (; e + 3 < s1; e += 4) {
        int sa = g_srcs[e],     sb = g_srcs[e + 1];
        int sc = g_srcs[e + 2], sd = g_srcs[e + 3];
        float4 va = __ldg(&hv[(size_t)sa * 32 + lane]);
        float4 vb = __ldg(&hv[(size_t)sb * 32 + lane]);
        float4 vc = __ldg(&hv[(size_t)sc * 32 + lane]);
        float4 vd = __ldg(&hv[(size_t)sd * 32 + lane]);
        acc.x += (va.x + vb.x) + (vc.x + vd.x);
        acc.y += (va.y + vb.y) + (vc.y + vd.y);
        acc.z += (va.z + vb.z) + (vc.z + vd.z);
        acc.w += (va.w + vb.w) + (vc.w + vd.w);
    }
    for (; e < s1; e++) {
        int sa = g_srcs[e];
        float4 va = __ldg(&hv[(size_t)sa * 32 + lane]);
        acc.x += va.x; acc.y += va.y; acc.z += va.z; acc.w += va.w;
    }
    // tf32-round so GEMM1 can cp.async the operand verbatim
    acc.x = __uint_as_float(f2tf(acc.x));
    acc.y = __uint_as_float(f2tf(acc.y));
    acc.z = __uint_as_float(f2tf(acc.z));
    acc.w = __uint_as_float(f2tf(acc.w));
    ((float4*)z)[(size_t)warp * 32 + lane] = acc;
}

// ---------------- tf32 mma.sync GEMM, cp.async staged ----------------------
// C = act(A[M,K] @ B[K,N] + bias). Block 128x128, 8 warps (4x2), warp 32x64.
// BK=32, 2-stage cp.async pipeline. A and B are pre-tf32 in gmem.
// ACT: 0 = none, 1 = leaky, 2 = leaky + tf32-round (output feeds next GEMM)
template <int K, int N, int ACT>
__global__ __launch_bounds__(256) void k_gemm(
    const float* __restrict__ A, const float* __restrict__ B,
    const float* __restrict__ bias, float* __restrict__ C)
{
    const int M = N_NODES;
    const int BK = 32;
    const int CHUNKS = K / BK;
    const int AS_STRIDE = 36;    // uints per row, 128 rows
    const int BS_STRIDE = 136;   // uints per row, 32 rows
    const int AS_SIZE = 128 * AS_STRIDE;   // 4608 uints
    const int BS_SIZE = 32 * BS_STRIDE;    // 4352 uints

    extern __shared__ uint32_t sm[];
    uint32_t* Asb[2] = { sm, sm + AS_SIZE };
    uint32_t* Bsb[2] = { sm + 2 * AS_SIZE, sm + 2 * AS_SIZE + BS_SIZE };

    int tid  = threadIdx.x;
    int warp = tid >> 5;
    int lane = tid & 31;
    int wm = warp >> 1;       // 0..3  (M offset 32*wm)
    int wn = warp & 1;        // 0..1  (N offset 64*wn)
    int g  = lane >> 2;       // 0..7
    int tg = lane & 3;        // 0..3
    int m0 = blockIdx.x * 128;
    int n0 = blockIdx.y * 128;

    auto stage = [&](int ch, int buf) {
        uint32_t abase = smem_u32(Asb[buf]);
        uint32_t bbase = smem_u32(Bsb[buf]);
#pragma unroll
        for (int j = 0; j < 4; j++) {
            int seg = tid + j * 256;
            int r   = seg >> 3;
            int cu  = (seg & 7) * 4;
            int gr  = m0 + r;
            uint32_t dst = abase + (uint32_t)(r * AS_STRIDE + cu) * 4u;
            const float* src = &A[(size_t)gr * K + ch * BK + cu];
            cp16z(dst, src, (gr < M) ? 16 : 0);
        }
#pragma unroll
        for (int j = 0; j < 4; j++) {
            int seg = tid + j * 256;
            int r   = seg >> 5;
            int cu  = (seg & 31) * 4;
            uint32_t dst = bbase + (uint32_t)(r * BS_STRIDE + cu) * 4u;
            const float* src = &B[(size_t)(ch * BK + r) * N + n0 + cu];
            cp16(dst, src);
        }
        CP_COMMIT();
    };

    // prologue: stage chunks 0 and 1
    stage(0, 0);
    if (CHUNKS > 1) stage(1, 1);

    float acc[2][8][4];
#pragma unroll
    for (int a = 0; a < 2; a++)
#pragma unroll
        for (int b = 0; b < 8; b++)
#pragma unroll
            for (int c = 0; c < 4; c++) acc[a][b][c] = 0.0f;

#pragma unroll
    for (int ch = 0; ch < CHUNKS; ch++) {
        const int buf = ch & 1;
        if (ch + 1 < CHUNKS) { CP_WAIT(1); } else { CP_WAIT(0); }
        __syncthreads();

        const uint32_t* As = Asb[buf];
        const uint32_t* Bs = Bsb[buf];
#pragma unroll
        for (int kk = 0; kk < BK; kk += 8) {
            uint32_t af[2][4], bf[8][2];
#pragma unroll
            for (int mt = 0; mt < 2; mt++) {
                int mr = wm * 32 + mt * 16 + g;
                af[mt][0] = As[mr * AS_STRIDE + kk + tg];
                af[mt][1] = As[(mr + 8) * AS_STRIDE + kk + tg];
                af[mt][2] = As[mr * AS_STRIDE + kk + tg + 4];
                af[mt][3] = As[(mr + 8) * AS_STRIDE + kk + tg + 4];
            }
#pragma unroll
            for (int nt = 0; nt < 8; nt++) {
                int nc = wn * 64 + nt * 8 + g;
                bf[nt][0] = Bs[(kk + tg) * BS_STRIDE + nc];
                bf[nt][1] = Bs[(kk + tg + 4) * BS_STRIDE + nc];
            }
#pragma unroll
            for (int mt = 0; mt < 2; mt++)
#pragma unroll
                for (int nt = 0; nt < 8; nt++)
                    mma8(acc[mt][nt], af[mt], bf[nt]);
        }
        __syncthreads();
        if (ch + 2 < CHUNKS) stage(ch + 2, buf);
    }

    // epilogue
#pragma unroll
    for (int mt = 0; mt < 2; mt++) {
#pragma unroll
        for (int nt = 0; nt < 8; nt++) {
            int row = m0 + wm * 32 + mt * 16 + g;
            int col = n0 + wn * 64 + nt * 8 + 2 * tg;
            float b0 = __ldg(&bias[col]);
            float b1 = __ldg(&bias[col + 1]);
            float v0 = acc[mt][nt][0] + b0;
            float v1 = acc[mt][nt][1] + b1;
            float v2 = acc[mt][nt][2] + b0;
            float v3 = acc[mt][nt][3] + b1;
            if (ACT >= 1) {
                v0 = lrelu(v0); v1 = lrelu(v1);
                v2 = lrelu(v2); v3 = lrelu(v3);
            }
            if (ACT == 2) {
                v0 = __uint_as_float(f2tf(v0));
                v1 = __uint_as_float(f2tf(v1));
                v2 = __uint_as_float(f2tf(v2));
                v3 = __uint_as_float(f2tf(v3));
            }
            if (row < M)
                *(float2*)&C[(size_t)row * N + col] = make_float2(v0, v1);
            if (row + 8 < M)
                *(float2*)&C[(size_t)(row + 8) * N + col] = make_float2(v2, v3);
        }
    }
}

// ---------------- launch ----------------
extern "C" void kernel_launch(void* const* d_in, const int* in_sizes, int n_in,
                              void* d_out, int out_size) {
    const float* x  = (const float*)d_in[0];
    const int*   ei = (const int*)d_in[1];     // int32 (JAX x64 disabled)
    const float* W1 = (const float*)d_in[2];
    const float* b1 = (const float*)d_in[3];
    const float* W2 = (const float*)d_in[4];
    const float* b2 = (const float*)d_in[5];
    float*       out = (float*)d_out;

    float *zp, *tp, *hp, *w1t, *w2t;
    cudaGetSymbolAddress((void**)&zp, g_z);
    cudaGetSymbolAddress((void**)&tp, g_t);
    cudaGetSymbolAddress((void**)&hp, g_h);
    cudaGetSymbolAddress((void**)&w1t, g_w1t);
    cudaGetSymbolAddress((void**)&w2t, g_w2t);

    const int SMEM = (2 * 128 * 36 + 2 * 32 * 136) * 4;   // 71680 B
    cudaFuncSetAttribute(k_gemm<128, 256, 2>, cudaFuncAttributeMaxDynamicSharedMemorySize, SMEM);
    cudaFuncSetAttribute(k_gemm<256, 128, 1>, cudaFuncAttributeMaxDynamicSharedMemorySize, SMEM);
    cudaFuncSetAttribute(k_gemm<256, 128, 0>, cudaFuncAttributeMaxDynamicSharedMemorySize, SMEM);

    // CSR build + weight tf32 convert (once per launch)
    k_zero_cnt<<<(N_NODES + 255) / 256, 256>>>();
    k_hist<<<(N_EDGES + 255) / 256, 256>>>(ei);
    k_wtrans<<<(2 * NUM_LAYER * 2 * D * D + 255) / 256, 256>>>(W1, W2);
    k_blocksum<<<N_SCAN_BLKS, SCAN_BLK>>>();
    k_scanblk<<<1, 256>>>();
    k_scatter<<<N_SCAN_BLKS, SCAN_BLK>>>();
    k_fill<<<(N_EDGES + 255) / 256, 256>>>(ei);

    const int M = N_NODES;
    const int MB = (M + 127) / 128;            // 391
    dim3 blk(256);
    dim3 grid_gather((N_NODES * 32 + 255) / 256);
    dim3 grid_g1(MB, 2);    // N=256, BN=128
    dim3 grid_g2(MB, 1);    // N=128, BN=128

    const float* hin = x;
    for (int l = 0; l < NUM_LAYER; l++) {
        k_gather<<<grid_gather, blk>>>(hin, zp);
        k_gemm<128, 256, 2><<<grid_g1, blk, SMEM>>>(zp, w1t + (size_t)l * D * 2 * D,
                                                    b1 + (size_t)l * 2 * D, tp);
        float* dst = (l == NUM_LAYER - 1) ? out : hp;
        if (l < NUM_LAYER - 1)
            k_gemm<256, 128, 1><<<grid_g2, blk, SMEM>>>(tp, w2t + (size_t)l * 2 * D * D,
                                                        b2 + (size_t)l * D, dst);
        else
            k_gemm<256, 128, 0><<<grid_g2, blk, SMEM>>>(tp, w2t + (size_t)l * 2 * D * D,
                                                        b2 + (size_t)l * D, dst);
        hin = hp;
    }
}

// round 9
// speedup vs baseline: 1.8099x; 1.4012x over previous
#include <cuda_runtime.h>
#include <cuda_fp16.h>
#include <cstdint>

#define N_NODES 50000
#define N_EDGES 600000
#define D 128
#define NUM_LAYER 5

#define SCAN_BLK 256
#define N_SCAN_BLKS ((N_NODES + SCAN_BLK - 1) / SCAN_BLK)   // 196

// ---------------- device scratch (allocation-free) ----------------
__device__ __half g_z[N_NODES * D];        // z = h + agg, fp16  (GEMM1 A)
__device__ __half g_t[N_NODES * 2 * D];    // hidden, fp16       (GEMM2 A)
__device__ float  g_h[N_NODES * D];        // layer output (f32, gather input)
__device__ int    g_cnt[N_NODES];
__device__ int    g_rowstart[N_NODES + 1];
__device__ int    g_cursor[N_NODES];
__device__ int    g_srcs[N_EDGES];
__device__ int    g_blksum[N_SCAN_BLKS];
__device__ int    g_blkoff[N_SCAN_BLKS];
__device__ __half g_w1t[NUM_LAYER * 2 * D * D];  // [l][n=256][k=128] fp16
__device__ __half g_w2t[NUM_LAYER * 2 * D * D];  // [l][n=128][k=256] fp16

// ---------------- helpers ----------------
__device__ __forceinline__ float lrelu(float v) { return v >= 0.0f ? v : 0.2f * v; }

__device__ __forceinline__ void mma16(float* c, const uint32_t* a, const uint32_t* b) {
    asm volatile(
        "mma.sync.aligned.m16n8k16.row.col.f32.f16.f16.f32 "
        "{%0,%1,%2,%3}, {%4,%5,%6,%7}, {%8,%9}, {%0,%1,%2,%3};"
        : "+f"(c[0]), "+f"(c[1]), "+f"(c[2]), "+f"(c[3])
        : "r"(a[0]), "r"(a[1]), "r"(a[2]), "r"(a[3]), "r"(b[0]), "r"(b[1]));
}

__device__ __forceinline__ uint32_t smem_u32(const void* p) {
    uint32_t a;
    asm("{ .reg .u64 t; cvta.to.shared.u64 t, %1; cvt.u32.u64 %0, t; }" : "=r"(a) : "l"(p));
    return a;
}
__device__ __forceinline__ void cp16(uint32_t s, const void* g) {
    asm volatile("cp.async.cg.shared.global [%0], [%1], 16;" :: "r"(s), "l"(g));
}
__device__ __forceinline__ void cp16z(uint32_t s, const void* g, int srcsz) {
    asm volatile("cp.async.cg.shared.global [%0], [%1], 16, %2;" :: "r"(s), "l"(g), "r"(srcsz));
}
#define CP_COMMIT() asm volatile("cp.async.commit_group;" ::: "memory")
#define CP_WAIT(n)  asm volatile("cp.async.wait_group %0;" :: "n"(n) : "memory")

// ---------------- CSR build (edge_index is int32: JAX x64 disabled) -------
__global__ void k_zero_cnt() {
    int i = blockIdx.x * blockDim.x + threadIdx.x;
    if (i < N_NODES) g_cnt[i] = 0;
}
__global__ void k_hist(const int* __restrict__ ei) {
    int e = blockIdx.x * blockDim.x + threadIdx.x;
    if (e < N_EDGES) {
        int dst = ei[N_EDGES + e];
        if ((unsigned)dst < N_NODES) atomicAdd(&g_cnt[dst], 1);
    }
}
__global__ void k_blocksum() {
    __shared__ int s[SCAN_BLK];
    int tid = threadIdx.x;
    int i = blockIdx.x * SCAN_BLK + tid;
    int v = (i < N_NODES) ? g_cnt[i] : 0;
    s[tid] = v;
    __syncthreads();
#pragma unroll
    for (int off = SCAN_BLK / 2; off > 0; off >>= 1) {
        if (tid < off) s[tid] += s[tid + off];
        __syncthreads();
    }
    if (tid == 0) g_blksum[blockIdx.x] = s[0];
}
__global__ void k_scanblk() {
    __shared__ int s[256];
    int tid = threadIdx.x;
    int v = (tid < N_SCAN_BLKS) ? g_blksum[tid] : 0;
    s[tid] = v;
    __syncthreads();
#pragma unroll
    for (int off = 1; off < 256; off <<= 1) {
        int t = (tid >= off) ? s[tid - off] : 0;
        __syncthreads();
        s[tid] += t;
        __syncthreads();
    }
    if (tid < N_SCAN_BLKS) g_blkoff[tid] = s[tid] - v;   // exclusive
    if (tid == 255) g_rowstart[N_NODES] = s[N_SCAN_BLKS - 1];
}
__global__ void k_scatter() {
    __shared__ int s[SCAN_BLK];
    int tid = threadIdx.x;
    int i = blockIdx.x * SCAN_BLK + tid;
    int v = (i < N_NODES) ? g_cnt[i] : 0;
    s[tid] = v;
    __syncthreads();
#pragma unroll
    for (int off = 1; off < SCAN_BLK; off <<= 1) {
        int t = (tid >= off) ? s[tid - off] : 0;
        __syncthreads();
        s[tid] += t;
        __syncthreads();
    }
    if (i < N_NODES) {
        int rs = g_blkoff[blockIdx.x] + s[tid] - v;   // exclusive
        g_rowstart[i] = rs;
        g_cursor[i]   = rs;
    }
}
__global__ void k_fill(const int* __restrict__ ei) {
    int e = blockIdx.x * blockDim.x + threadIdx.x;
    if (e < N_EDGES) {
        int src = ei[e];
        int dst = ei[N_EDGES + e];
        if ((unsigned)dst < N_NODES && (unsigned)src < N_NODES) {
            int p = atomicAdd(&g_cursor[dst], 1);
            g_srcs[p] = src;
        }
    }
}

// ------ weight transpose + fp16 convert: w[l][k][n] -> wt[l][n][k] ---------
__global__ void k_wtrans(const float* __restrict__ W1, const float* __restrict__ W2) {
    const int HALF = NUM_LAYER * 2 * D * D;   // 163840
    int i = blockIdx.x * blockDim.x + threadIdx.x;
    if (i < HALF) {
        int l = i / (2 * D * D);
        int r = i % (2 * D * D);
        int n = r / D;            // 0..255
        int k = r % D;            // 0..127
        g_w1t[i] = __float2half_rn(W1[(size_t)l * 2 * D * D + (size_t)k * (2 * D) + n]);
    } else if (i < 2 * HALF) {
        int j = i - HALF;
        int l = j / (2 * D * D);
        int r = j % (2 * D * D);
        int n = r / (2 * D);      // 0..127
        int k = r % (2 * D);      // 0..255
        g_w2t[j] = __float2half_rn(W2[(size_t)l * 2 * D * D + (size_t)k * D + n]);
    }
}

// ------ gather: z[n] = fp16(h[n] + sum_{src->n} h[src]), fp32 accumulate ---
__global__ void k_gather(const float* __restrict__ h, __half* __restrict__ z) {
    int warp = (blockIdx.x * blockDim.x + threadIdx.x) >> 5;
    int lane = threadIdx.x & 31;
    if (warp >= N_NODES) return;
    const float4* hv = (const float4*)h;
    int s0 = g_rowstart[warp];
    int s1 = g_rowstart[warp + 1];
    float4 acc = __ldg(&hv[(size_t)warp * 32 + lane]);
    int e = s0;
    for (; e + 3 < s1; e += 4) {
        int sa = g_srcs[e],     sb = g_srcs[e + 1];
        int sc = g_srcs[e + 2], sd = g_srcs[e + 3];
        float4 va = __ldg(&hv[(size_t)sa * 32 + lane]);
        float4 vb = __ldg(&hv[(size_t)sb * 32 + lane]);
        float4 vc = __ldg(&hv[(size_t)sc * 32 + lane]);
        float4 vd = __ldg(&hv[(size_t)sd * 32 + lane]);
        acc.x += (va.x + vb.x) + (vc.x + vd.x);
        acc.y += (va.y + vb.y) + (vc.y + vd.y);
        acc.z += (va.z + vb.z) + (vc.z + vd.z);
        acc.w += (va.w + vb.w) + (vc.w + vd.w);
    }
    for (; e < s1; e++) {
        int sa = g_srcs[e];
        float4 va = __ldg(&hv[(size_t)sa * 32 + lane]);
        acc.x += va.x; acc.y += va.y; acc.z += va.z; acc.w += va.w;
    }
    __half2 p0 = make_half2(__float2half_rn(acc.x), __float2half_rn(acc.y));
    __half2 p1 = make_half2(__float2half_rn(acc.z), __float2half_rn(acc.w));
    uint2 pk;
    pk.x = *(uint32_t*)&p0;
    pk.y = *(uint32_t*)&p1;
    *(uint2*)&z[(size_t)warp * D + 4 * lane] = pk;
}

// ---------------- fp16 mma.sync GEMM, cp.async staged ----------------------
// C = act(A[M,K] @ Bt[N,K]^T + bias). Block 128x128, 8 warps (4x2), warp 32x64.
// BK=64, 2-stage cp.async pipeline. A fp16 [M][K], Bt fp16 [N][K].
// MODE: 0 = f32 out, no act; 1 = f32 out, leaky; 2 = fp16 out, leaky
template <int K, int N, int MODE>
__global__ __launch_bounds__(256) void k_gemm(
    const __half* __restrict__ A, const __half* __restrict__ Bt,
    const float* __restrict__ bias, void* __restrict__ Cv)
{
    const int M = N_NODES;
    const int BK = 64;
    const int CHUNKS = K / BK;
    const int STRIDE = 72;                  // halfs per row (64 + 8 pad); 144B, 16B-aligned
    const int TILE = 128 * STRIDE;          // halfs per tile

    extern __shared__ __half sh[];
    __half* Asb[2] = { sh, sh + TILE };
    __half* Bsb[2] = { sh + 2 * TILE, sh + 3 * TILE };

    int tid  = threadIdx.x;
    int warp = tid >> 5;
    int lane = tid & 31;
    int wm = warp >> 1;       // 0..3  (M offset 32*wm)
    int wn = warp & 1;        // 0..1  (N offset 64*wn)
    int g  = lane >> 2;       // 0..7
    int tg = lane & 3;        // 0..3
    int m0 = blockIdx.x * 128;
    int n0 = blockIdx.y * 128;

    auto stage = [&](int ch, int buf) {
        uint32_t abase = smem_u32(Asb[buf]);
        uint32_t bbase = smem_u32(Bsb[buf]);
#pragma unroll
        for (int j = 0; j < 4; j++) {
            int seg = tid + j * 256;        // 0..1023
            int r   = seg >> 3;             // 0..127
            int c16 = seg & 7;              // 16B unit within 128B row
            int gr  = m0 + r;
            uint32_t dst = abase + (uint32_t)(r * STRIDE * 2 + c16 * 16);
            const __half* src = &A[(size_t)gr * K + ch * BK + c16 * 8];
            cp16z(dst, src, (gr < M) ? 16 : 0);
        }
#pragma unroll
        for (int j = 0; j < 4; j++) {
            int seg = tid + j * 256;
            int r   = seg >> 3;             // n-row 0..127
            int c16 = seg & 7;
            uint32_t dst = bbase + (uint32_t)(r * STRIDE * 2 + c16 * 16);
            const __half* src = &Bt[(size_t)(n0 + r) * K + ch * BK + c16 * 8];
            cp16(dst, src);
        }
        CP_COMMIT();
    };

    stage(0, 0);
    if (CHUNKS > 1) stage(1, 1);

    float acc[2][8][4];
#pragma unroll
    for (int a = 0; a < 2; a++)
#pragma unroll
        for (int b = 0; b < 8; b++)
#pragma unroll
            for (int c = 0; c < 4; c++) acc[a][b][c] = 0.0f;

#pragma unroll
    for (int ch = 0; ch < CHUNKS; ch++) {
        const int buf = ch & 1;
        if (ch + 1 < CHUNKS) { CP_WAIT(1); } else { CP_WAIT(0); }
        __syncthreads();

        const __half* As = Asb[buf];
        const __half* Bs = Bsb[buf];
#pragma unroll
        for (int kk = 0; kk < BK; kk += 16) {
            uint32_t af[2][4], bf[8][2];
#pragma unroll
            for (int mt = 0; mt < 2; mt++) {
                int mr = wm * 32 + mt * 16 + g;
                af[mt][0] = *(const uint32_t*)&As[mr * STRIDE + kk + 2 * tg];
                af[mt][1] = *(const uint32_t*)&As[(mr + 8) * STRIDE + kk + 2 * tg];
                af[mt][2] = *(const uint32_t*)&As[mr * STRIDE + kk + 2 * tg + 8];
                af[mt][3] = *(const uint32_t*)&As[(mr + 8) * STRIDE + kk + 2 * tg + 8];
            }
#pragma unroll
            for (int nt = 0; nt < 8; nt++) {
                int nc = wn * 64 + nt * 8 + g;
                bf[nt][0] = *(const uint32_t*)&Bs[nc * STRIDE + kk + 2 * tg];
                bf[nt][1] = *(const uint32_t*)&Bs[nc * STRIDE + kk + 2 * tg + 8];
            }
#pragma unroll
            for (int mt = 0; mt < 2; mt++)
#pragma unroll
                for (int nt = 0; nt < 8; nt++)
                    mma16(acc[mt][nt], af[mt], bf[nt]);
        }
        __syncthreads();
        if (ch + 2 < CHUNKS) stage(ch + 2, buf);
    }

    // epilogue
#pragma unroll
    for (int mt = 0; mt < 2; mt++) {
#pragma unroll
        for (int nt = 0; nt < 8; nt++) {
            int row = m0 + wm * 32 + mt * 16 + g;
            int col = n0 + wn * 64 + nt * 8 + 2 * tg;
            float b0 = __ldg(&bias[col]);
            float b1 = __ldg(&bias[col + 1]);
            float v0 = acc[mt][nt][0] + b0;
            float v1 = acc[mt][nt][1] + b1;
            float v2 = acc[mt][nt][2] + b0;
            float v3 = acc[mt][nt][3] + b1;
            if (MODE >= 1) {
                v0 = lrelu(v0); v1 = lrelu(v1);
                v2 = lrelu(v2); v3 = lrelu(v3);
            }
            if (MODE == 2) {
                __half* C = (__half*)Cv;
                __half2 pa = make_half2(__float2half_rn(v0), __float2half_rn(v1));
                __half2 pb = make_half2(__float2half_rn(v2), __float2half_rn(v3));
                if (row < M)     *(uint32_t*)&C[(size_t)row * N + col]       = *(uint32_t*)&pa;
                if (row + 8 < M) *(uint32_t*)&C[(size_t)(row + 8) * N + col] = *(uint32_t*)&pb;
            } else {
                float* C = (float*)Cv;
                if (row < M)     *(float2*)&C[(size_t)row * N + col]       = make_float2(v0, v1);
                if (row + 8 < M) *(float2*)&C[(size_t)(row + 8) * N + col] = make_float2(v2, v3);
            }
        }
    }
}

// ---- first-layer input conversion: x (f32) feeds gather directly (h = x) --
// (gather reads f32, so no conversion kernel needed)

// ---------------- launch ----------------
extern "C" void kernel_launch(void* const* d_in, const int* in_sizes, int n_in,
                              void* d_out, int out_size) {
    const float* x  = (const float*)d_in[0];
    const int*   ei = (const int*)d_in[1];     // int32 (JAX x64 disabled)
    const float* W1 = (const float*)d_in[2];
    const float* b1 = (const float*)d_in[3];
    const float* W2 = (const float*)d_in[4];
    const float* b2 = (const float*)d_in[5];
    float*       out = (float*)d_out;

    __half *zp, *tp, *w1t, *w2t;
    float  *hp;
    cudaGetSymbolAddress((void**)&zp, g_z);
    cudaGetSymbolAddress((void**)&tp, g_t);
    cudaGetSymbolAddress((void**)&hp, g_h);
    cudaGetSymbolAddress((void**)&w1t, g_w1t);
    cudaGetSymbolAddress((void**)&w2t, g_w2t);

    const int SMEM = 4 * 128 * 72 * 2;   // 73728 B (2 bufs x (A+B) x 128 rows x 72 halfs)
    cudaFuncSetAttribute(k_gemm<128, 256, 2>, cudaFuncAttributeMaxDynamicSharedMemorySize, SMEM);
    cudaFuncSetAttribute(k_gemm<256, 128, 1>, cudaFuncAttributeMaxDynamicSharedMemorySize, SMEM);
    cudaFuncSetAttribute(k_gemm<256, 128, 0>, cudaFuncAttributeMaxDynamicSharedMemorySize, SMEM);

    // CSR build + weight transpose/convert (once per launch)
    k_zero_cnt<<<(N_NODES + 255) / 256, 256>>>();
    k_hist<<<(N_EDGES + 255) / 256, 256>>>(ei);
    k_wtrans<<<(2 * NUM_LAYER * 2 * D * D + 255) / 256, 256>>>(W1, W2);
    k_blocksum<<<N_SCAN_BLKS, SCAN_BLK>>>();
    k_scanblk<<<1, 256>>>();
    k_scatter<<<N_SCAN_BLKS, SCAN_BLK>>>();
    k_fill<<<(N_EDGES + 255) / 256, 256>>>(ei);

    const int M = N_NODES;
    const int MB = (M + 127) / 128;            // 391
    dim3 blk(256);
    dim3 grid_gather((N_NODES * 32 + 255) / 256);
    dim3 grid_g1(MB, 2);    // N=256, BN=128
    dim3 grid_g2(MB, 1);    // N=128, BN=128

    const float* hin = x;
    for (int l = 0; l < NUM_LAYER; l++) {
        k_gather<<<grid_gather, blk>>>(hin, zp);
        k_gemm<128, 256, 2><<<grid_g1, blk, SMEM>>>(zp, w1t + (size_t)l * 2 * D * D,
                                                    b1 + (size_t)l * 2 * D, (void*)tp);
        float* dst = (l == NUM_LAYER - 1) ? out : hp;
        if (l < NUM_LAYER - 1)
            k_gemm<256, 128, 1><<<grid_g2, blk, SMEM>>>(tp, w2t + (size_t)l * 2 * D * D,
                                                        b2 + (size_t)l * D, (void*)dst);
        else
            k_gemm<256, 128, 0><<<grid_g2, blk, SMEM>>>(tp, w2t + (size_t)l * 2 * D * D,
                                                        b2 + (size_t)l * D, (void*)dst);
        hin = hp;
    }
}

// round 11
// speedup vs baseline: 1.8308x; 1.0116x over previous
#include <cuda_runtime.h>
#include <cuda_fp16.h>
#include <cstdint>

#define N_NODES 50000
#define N_EDGES 600000
#define D 128
#define NUM_LAYER 5

#define SCAN_BLK 256
#define N_SCAN_BLKS ((N_NODES + SCAN_BLK - 1) / SCAN_BLK)   // 196

// ---------------- device scratch (allocation-free) ----------------
__device__ __half g_z[N_NODES * D];        // z = h + agg, fp16  (GEMM1 A)
__device__ __half g_t[N_NODES * 2 * D];    // hidden, fp16       (GEMM2 A)
__device__ __half g_hx[N_NODES * D];       // layer io, fp16 (gather input / GEMM2 out)
__device__ int    g_cnt[N_NODES];
__device__ int    g_rowstart[N_NODES + 1];
__device__ int    g_cursor[N_NODES];
__device__ int    g_srcs[N_EDGES];
__device__ int    g_blksum[N_SCAN_BLKS];
__device__ int    g_blkoff[N_SCAN_BLKS];
__device__ __half g_w1t[NUM_LAYER * 2 * D * D];  // [l][n=256][k=128] fp16
__device__ __half g_w2t[NUM_LAYER * 2 * D * D];  // [l][n=128][k=256] fp16

// ---------------- helpers ----------------
__device__ __forceinline__ float lrelu(float v) { return v >= 0.0f ? v : 0.2f * v; }

__device__ __forceinline__ void mma16(float* c, const uint32_t* a, const uint32_t* b) {
    asm volatile(
        "mma.sync.aligned.m16n8k16.row.col.f32.f16.f16.f32 "
        "{%0,%1,%2,%3}, {%4,%5,%6,%7}, {%8,%9}, {%0,%1,%2,%3};"
        : "+f"(c[0]), "+f"(c[1]), "+f"(c[2]), "+f"(c[3])
        : "r"(a[0]), "r"(a[1]), "r"(a[2]), "r"(a[3]), "r"(b[0]), "r"(b[1]));
}

__device__ __forceinline__ uint32_t smem_u32(const void* p) {
    uint32_t a;
    asm("{ .reg .u64 t; cvta.to.shared.u64 t, %1; cvt.u32.u64 %0, t; }" : "=r"(a) : "l"(p));
    return a;
}
__device__ __forceinline__ void cp16(uint32_t s, const void* g) {
    asm volatile("cp.async.cg.shared.global [%0], [%1], 16;" :: "r"(s), "l"(g));
}
__device__ __forceinline__ void cp16z(uint32_t s, const void* g, int srcsz) {
    asm volatile("cp.async.cg.shared.global [%0], [%1], 16, %2;" :: "r"(s), "l"(g), "r"(srcsz));
}
#define CP_COMMIT() asm volatile("cp.async.commit_group;" ::: "memory")
#define CP_WAIT(n)  asm volatile("cp.async.wait_group %0;" :: "n"(n) : "memory")

// ---------------- CSR build (edge_index is int32: JAX x64 disabled) -------
__global__ void k_zero_cnt() {
    int i = blockIdx.x * blockDim.x + threadIdx.x;
    if (i < N_NODES) g_cnt[i] = 0;
}
__global__ void k_hist(const int* __restrict__ ei) {
    int e = blockIdx.x * blockDim.x + threadIdx.x;
    if (e < N_EDGES) {
        int dst = ei[N_EDGES + e];
        if ((unsigned)dst < N_NODES) atomicAdd(&g_cnt[dst], 1);
    }
}
__global__ void k_blocksum() {
    __shared__ int s[SCAN_BLK];
    int tid = threadIdx.x;
    int i = blockIdx.x * SCAN_BLK + tid;
    int v = (i < N_NODES) ? g_cnt[i] : 0;
    s[tid] = v;
    __syncthreads();
#pragma unroll
    for (int off = SCAN_BLK / 2; off > 0; off >>= 1) {
        if (tid < off) s[tid] += s[tid + off];
        __syncthreads();
    }
    if (tid == 0) g_blksum[blockIdx.x] = s[0];
}
__global__ void k_scanblk() {
    __shared__ int s[256];
    int tid = threadIdx.x;
    int v = (tid < N_SCAN_BLKS) ? g_blksum[tid] : 0;
    s[tid] = v;
    __syncthreads();
#pragma unroll
    for (int off = 1; off < 256; off <<= 1) {
        int t = (tid >= off) ? s[tid - off] : 0;
        __syncthreads();
        s[tid] += t;
        __syncthreads();
    }
    if (tid < N_SCAN_BLKS) g_blkoff[tid] = s[tid] - v;   // exclusive
    if (tid == 255) g_rowstart[N_NODES] = s[N_SCAN_BLKS - 1];
}
__global__ void k_scatter() {
    __shared__ int s[SCAN_BLK];
    int tid = threadIdx.x;
    int i = blockIdx.x * SCAN_BLK + tid;
    int v = (i < N_NODES) ? g_cnt[i] : 0;
    s[tid] = v;
    __syncthreads();
#pragma unroll
    for (int off = 1; off < SCAN_BLK; off <<= 1) {
        int t = (tid >= off) ? s[tid - off] : 0;
        __syncthreads();
        s[tid] += t;
        __syncthreads();
    }
    if (i < N_NODES) {
        int rs = g_blkoff[blockIdx.x] + s[tid] - v;   // exclusive
        g_rowstart[i] = rs;
        g_cursor[i]   = rs;
    }
}
__global__ void k_fill(const int* __restrict__ ei) {
    int e = blockIdx.x * blockDim.x + threadIdx.x;
    if (e < N_EDGES) {
        int src = ei[e];
        int dst = ei[N_EDGES + e];
        if ((unsigned)dst < N_NODES && (unsigned)src < N_NODES) {
            int p = atomicAdd(&g_cursor[dst], 1);
            g_srcs[p] = src;
        }
    }
}

// ------ weight transpose + fp16 convert: w[l][k][n] -> wt[l][n][k] ---------
__global__ void k_wtrans(const float* __restrict__ W1, const float* __restrict__ W2) {
    const int HALF = NUM_LAYER * 2 * D * D;   // 163840
    int i = blockIdx.x * blockDim.x + threadIdx.x;
    if (i < HALF) {
        int l = i / (2 * D * D);
        int r = i % (2 * D * D);
        int n = r / D;            // 0..255
        int k = r % D;            // 0..127
        g_w1t[i] = __float2half_rn(W1[(size_t)l * 2 * D * D + (size_t)k * (2 * D) + n]);
    } else if (i < 2 * HALF) {
        int j = i - HALF;
        int l = j / (2 * D * D);
        int r = j % (2 * D * D);
        int n = r / (2 * D);      // 0..127
        int k = r % (2 * D);      // 0..255
        g_w2t[j] = __float2half_rn(W2[(size_t)l * 2 * D * D + (size_t)k * D + n]);
    }
}

// ------ x (f32) -> fp16 conversion (first-layer gather input) --------------
__global__ void k_xconv(const float* __restrict__ x, __half* __restrict__ xh) {
    int i = blockIdx.x * blockDim.x + threadIdx.x;   // over N*D/4
    if (i < N_NODES * D / 4) {
        float4 v = __ldg(&((const float4*)x)[i]);
        __half2 p0 = make_half2(__float2half_rn(v.x), __float2half_rn(v.y));
        __half2 p1 = make_half2(__float2half_rn(v.z), __float2half_rn(v.w));
        uint2 pk;
        pk.x = *(uint32_t*)&p0;
        pk.y = *(uint32_t*)&p1;
        ((uint2*)xh)[i] = pk;
    }
}

// ------ gather (fp16 in/out, fp32 accum): z[n] = h[n] + sum h[src] ---------
__global__ void k_gather16(const __half* __restrict__ h, __half* __restrict__ z) {
    int warp = (blockIdx.x * blockDim.x + threadIdx.x) >> 5;
    int lane = threadIdx.x & 31;
    if (warp >= N_NODES) return;
    const uint2* hv = (const uint2*)h;     // 4 halfs per uint2; 32 uint2 per row
    int s0 = g_rowstart[warp];
    int s1 = g_rowstart[warp + 1];

    uint2 u = __ldg(&hv[(size_t)warp * 32 + lane]);
    float2 a0 = __half22float2(*(__half2*)&u.x);
    float2 a1 = __half22float2(*(__half2*)&u.y);
    float ax = a0.x, ay = a0.y, az = a1.x, aw = a1.y;

    int e = s0;
    for (; e + 3 < s1; e += 4) {
        int sa = g_srcs[e],     sb = g_srcs[e + 1];
        int sc = g_srcs[e + 2], sd = g_srcs[e + 3];
        uint2 va = __ldg(&hv[(size_t)sa * 32 + lane]);
        uint2 vb = __ldg(&hv[(size_t)sb * 32 + lane]);
        uint2 vc = __ldg(&hv[(size_t)sc * 32 + lane]);
        uint2 vd = __ldg(&hv[(size_t)sd * 32 + lane]);
        float2 fa0 = __half22float2(*(__half2*)&va.x), fa1 = __half22float2(*(__half2*)&va.y);
        float2 fb0 = __half22float2(*(__half2*)&vb.x), fb1 = __half22float2(*(__half2*)&vb.y);
        float2 fc0 = __half22float2(*(__half2*)&vc.x), fc1 = __half22float2(*(__half2*)&vc.y);
        float2 fd0 = __half22float2(*(__half2*)&vd.x), fd1 = __half22float2(*(__half2*)&vd.y);
        ax += (fa0.x + fb0.x) + (fc0.x + fd0.x);
        ay += (fa0.y + fb0.y) + (fc0.y + fd0.y);
        az += (fa1.x + fb1.x) + (fc1.x + fd1.x);
        aw += (fa1.y + fb1.y) + (fc1.y + fd1.y);
    }
    for (; e < s1; e++) {
        int sa = g_srcs[e];
        uint2 va = __ldg(&hv[(size_t)sa * 32 + lane]);
        float2 fa0 = __half22float2(*(__half2*)&va.x), fa1 = __half22float2(*(__half2*)&va.y);
        ax += fa0.x; ay += fa0.y; az += fa1.x; aw += fa1.y;
    }
    __half2 p0 = make_half2(__float2half_rn(ax), __float2half_rn(ay));
    __half2 p1 = make_half2(__float2half_rn(az), __float2half_rn(aw));
    uint2 pk;
    pk.x = *(uint32_t*)&p0;
    pk.y = *(uint32_t*)&p1;
    ((uint2*)z)[(size_t)warp * 32 + lane] = pk;
}

// ---------------- fp16 mma.sync GEMM, cp.async staged ----------------------
// C = act(A[M,K] @ Bt[N,K]^T + bias). Block 128x128, 8 warps (4x2), warp 32x64.
// BK=64, 2-stage cp.async pipeline. A fp16 [M][K], Bt fp16 [N][K].
// MODE: 0 = f32 out, no act; 1 = f32 out, leaky; 2 = fp16 out, leaky
template <int K, int N, int MODE>
__global__ __launch_bounds__(256) void k_gemm(
    const __half* __restrict__ A, const __half* __restrict__ Bt,
    const float* __restrict__ bias, void* __restrict__ Cv)
{
    const int M = N_NODES;
    const int BK = 64;
    const int CHUNKS = K / BK;
    const int STRIDE = 72;                  // halfs per row (64 + 8 pad)
    const int TILE = 128 * STRIDE;

    extern __shared__ __half sh[];
    __half* Asb[2] = { sh, sh + TILE };
    __half* Bsb[2] = { sh + 2 * TILE, sh + 3 * TILE };

    int tid  = threadIdx.x;
    int warp = tid >> 5;
    int lane = tid & 31;
    int wm = warp >> 1;
    int wn = warp & 1;
    int g  = lane >> 2;
    int tg = lane & 3;
    int m0 = blockIdx.x * 128;
    int n0 = blockIdx.y * 128;

    auto stage = [&](int ch, int buf) {
        uint32_t abase = smem_u32(Asb[buf]);
        uint32_t bbase = smem_u32(Bsb[buf]);
#pragma unroll
        for (int j = 0; j < 4; j++) {
            int seg = tid + j * 256;
            int r   = seg >> 3;
            int c16 = seg & 7;
            int gr  = m0 + r;
            uint32_t dst = abase + (uint32_t)(r * STRIDE * 2 + c16 * 16);
            const __half* src = &A[(size_t)gr * K + ch * BK + c16 * 8];
            cp16z(dst, src, (gr < M) ? 16 : 0);
        }
#pragma unroll
        for (int j = 0; j < 4; j++) {
            int seg = tid + j * 256;
            int r   = seg >> 3;
            int c16 = seg & 7;
            uint32_t dst = bbase + (uint32_t)(r * STRIDE * 2 + c16 * 16);
            const __half* src = &Bt[(size_t)(n0 + r) * K + ch * BK + c16 * 8];
            cp16(dst, src);
        }
        CP_COMMIT();
    };

    stage(0, 0);
    if (CHUNKS > 1) stage(1, 1);

    float acc[2][8][4];
#pragma unroll
    for (int a = 0; a < 2; a++)
#pragma unroll
        for (int b = 0; b < 8; b++)
#pragma unroll
            for (int c = 0; c < 4; c++) acc[a][b][c] = 0.0f;

#pragma unroll
    for (int ch = 0; ch < CHUNKS; ch++) {
        const int buf = ch & 1;
        if (ch + 1 < CHUNKS) { CP_WAIT(1); } else { CP_WAIT(0); }
        __syncthreads();

        const __half* As = Asb[buf];
        const __half* Bs = Bsb[buf];
#pragma unroll
        for (int kk = 0; kk < BK; kk += 16) {
            uint32_t af[2][4], bf[8][2];
#pragma unroll
            for (int mt = 0; mt < 2; mt++) {
                int mr = wm * 32 + mt * 16 + g;
                af[mt][0] = *(const uint32_t*)&As[mr * STRIDE + kk + 2 * tg];
                af[mt][1] = *(const uint32_t*)&As[(mr + 8) * STRIDE + kk + 2 * tg];
                af[mt][2] = *(const uint32_t*)&As[mr * STRIDE + kk + 2 * tg + 8];
                af[mt][3] = *(const uint32_t*)&As[(mr + 8) * STRIDE + kk + 2 * tg + 8];
            }
#pragma unroll
            for (int nt = 0; nt < 8; nt++) {
                int nc = wn * 64 + nt * 8 + g;
                bf[nt][0] = *(const uint32_t*)&Bs[nc * STRIDE + kk + 2 * tg];
                bf[nt][1] = *(const uint32_t*)&Bs[nc * STRIDE + kk + 2 * tg + 8];
            }
#pragma unroll
            for (int mt = 0; mt < 2; mt++)
#pragma unroll
                for (int nt = 0; nt < 8; nt++)
                    mma16(acc[mt][nt], af[mt], bf[nt]);
        }
        __syncthreads();
        if (ch + 2 < CHUNKS) stage(ch + 2, buf);
    }

    // epilogue
#pragma unroll
    for (int mt = 0; mt < 2; mt++) {
#pragma unroll
        for (int nt = 0; nt < 8; nt++) {
            int row = m0 + wm * 32 + mt * 16 + g;
            int col = n0 + wn * 64 + nt * 8 + 2 * tg;
            float b0 = __ldg(&bias[col]);
            float b1 = __ldg(&bias[col + 1]);
            float v0 = acc[mt][nt][0] + b0;
            float v1 = acc[mt][nt][1] + b1;
            float v2 = acc[mt][nt][2] + b0;
            float v3 = acc[mt][nt][3] + b1;
            if (MODE >= 1) {
                v0 = lrelu(v0); v1 = lrelu(v1);
                v2 = lrelu(v2); v3 = lrelu(v3);
            }
            if (MODE == 2) {
                __half* C = (__half*)Cv;
                __half2 pa = make_half2(__float2half_rn(v0), __float2half_rn(v1));
                __half2 pb = make_half2(__float2half_rn(v2), __float2half_rn(v3));
                if (row < M)     *(uint32_t*)&C[(size_t)row * N + col]       = *(uint32_t*)&pa;
                if (row + 8 < M) *(uint32_t*)&C[(size_t)(row + 8) * N + col] = *(uint32_t*)&pb;
            } else {
                float* C = (float*)Cv;
                if (row < M)     *(float2*)&C[(size_t)row * N + col]       = make_float2(v0, v1);
                if (row + 8 < M) *(float2*)&C[(size_t)(row + 8) * N + col] = make_float2(v2, v3);
            }
        }
    }
}

// ---------------- launch ----------------
extern "C" void kernel_launch(void* const* d_in, const int* in_sizes, int n_in,
                              void* d_out, int out_size) {
    const float* x  = (const float*)d_in[0];
    const int*   ei = (const int*)d_in[1];     // int32 (JAX x64 disabled)
    const float* W1 = (const float*)d_in[2];
    const float* b1 = (const float*)d_in[3];
    const float* W2 = (const float*)d_in[4];
    const float* b2 = (const float*)d_in[5];
    float*       out = (float*)d_out;

    __half *zp, *tp, *hxp, *w1t, *w2t;
    cudaGetSymbolAddress((void**)&zp, g_z);
    cudaGetSymbolAddress((void**)&tp, g_t);
    cudaGetSymbolAddress((void**)&hxp, g_hx);
    cudaGetSymbolAddress((void**)&w1t, g_w1t);
    cudaGetSymbolAddress((void**)&w2t, g_w2t);

    const int SMEM = 4 * 128 * 72 * 2;   // 73728 B
    cudaFuncSetAttribute(k_gemm<128, 256, 2>, cudaFuncAttributeMaxDynamicSharedMemorySize, SMEM);
    cudaFuncSetAttribute(k_gemm<256, 128, 2>, cudaFuncAttributeMaxDynamicSharedMemorySize, SMEM);
    cudaFuncSetAttribute(k_gemm<256, 128, 0>, cudaFuncAttributeMaxDynamicSharedMemorySize, SMEM);

    // CSR build + weight transpose/convert + x conversion (once per launch)
    k_zero_cnt<<<(N_NODES + 255) / 256, 256>>>();
    k_hist<<<(N_EDGES + 255) / 256, 256>>>(ei);
    k_wtrans<<<(2 * NUM_LAYER * 2 * D * D + 255) / 256, 256>>>(W1, W2);
    k_xconv<<<(N_NODES * D / 4 + 255) / 256, 256>>>(x, hxp);
    k_blocksum<<<N_SCAN_BLKS, SCAN_BLK>>>();
    k_scanblk<<<1, 256>>>();
    k_scatter<<<N_SCAN_BLKS, SCAN_BLK>>>();
    k_fill<<<(N_EDGES + 255) / 256, 256>>>(ei);

    const int M = N_NODES;
    const int MB = (M + 127) / 128;            // 391
    dim3 blk(256);
    dim3 grid_gather((N_NODES * 32 + 255) / 256);
    dim3 grid_g1(MB, 2);    // N=256, BN=128
    dim3 grid_g2(MB, 1);    // N=128, BN=128

    for (int l = 0; l < NUM_LAYER; l++) {
        k_gather16<<<grid_gather, blk>>>(hxp, zp);
        k_gemm<128, 256, 2><<<grid_g1, blk, SMEM>>>(zp, w1t + (size_t)l * 2 * D * D,
                                                    b1 + (size_t)l * 2 * D, (void*)tp);
        if (l < NUM_LAYER - 1)
            k_gemm<256, 128, 2><<<grid_g2, blk, SMEM>>>(tp, w2t + (size_t)l * 2 * D * D,
                                                        b2 + (size_t)l * D, (void*)hxp);
        else
            k_gemm<256, 128, 0><<<grid_g2, blk, SMEM>>>(tp, w2t + (size_t)l * 2 * D * D,
                                                        b2 + (size_t)l * D, (void*)out);
    }
}